// round 3
// baseline (speedup 1.0000x reference)
#include <cuda_runtime.h>

// GenSP superpixel affinity — GB300 sm_103a
// B=4, C=64, H=W=256, stoken=16 -> nH=nW=16, nS=256, P=65536
#define BB    4
#define CC    64
#define HH    256
#define WW    256
#define NHB   16
#define NS    256
#define PP    65536
#define FP2   258           // padded smem stride (floats) for transposed feat reads

typedef unsigned long long u64;

__device__ __forceinline__ u64 pack2(float lo, float hi) {
    u64 r; asm("mov.b64 %0, {%1,%2};" : "=l"(r) : "f"(lo), "f"(hi)); return r;
}
__device__ __forceinline__ void unpack2(u64 v, float& lo, float& hi) {
    asm("mov.b64 {%0,%1}, %2;" : "=f"(lo), "=f"(hi) : "l"(v));
}
__device__ __forceinline__ void ffma2(u64& d, u64 a, u64 b) {
    asm("fma.rn.f32x2 %0, %1, %2, %0;" : "+l"(d) : "l"(a), "l"(b));
}

// ---------------- device scratch ------------------------------------------
__device__ float g_cent[BB * NS * CC];
__device__ float g_num [BB * NS * CC];
__device__ float g_den [BB * NS];
__device__ float g_aff [BB * 9 * PP];     // iter-1 affinities [b][k][p]

// ---------------- K1: block means + zero num/den --------------------------
__global__ __launch_bounds__(256) void k_cent0(const float* __restrict__ x) {
    int blk = blockIdx.x;                  // b*256 + s
    int b = blk >> 8, s = blk & 255;
    int si = s >> 4, sj = s & 15;
    int t = threadIdx.x, w = t >> 5, lane = t & 31;

    if (t < CC)  g_num[blk * CC + t] = 0.f;
    if (t == CC) g_den[blk] = 0.f;

    const float* xb = x + (size_t)b * CC * PP + (size_t)(si * 16) * WW + sj * 16;
    #pragma unroll
    for (int cc = 0; cc < 8; cc++) {
        int c = w * 8 + cc;
        const float4* xc = (const float4*)(xb + (size_t)c * PP);
        float sum = 0.f;
        #pragma unroll
        for (int q = 0; q < 2; q++) {
            int i = lane + q * 32;          // 0..63 float4 per tile-channel
            int row = i >> 2, col = i & 3;
            float4 f = xc[row * (WW >> 2) + col];
            sum += (f.x + f.y) + (f.z + f.w);
        }
        #pragma unroll
        for (int o = 16; o; o >>= 1) sum += __shfl_xor_sync(0xffffffffu, sum, o);
        if (lane == 0) g_cent[blk * CC + c] = sum * (1.f / 256.f);
    }
}

// ---------------- K2: affinity iter0 + num/den (one tile per CTA) ---------
// dyn smem: cent2[9*32] u64 | c2s[16] f | feats[64*FP2] f | aff[9*256] f
#define SM0_BYTES (288 * 8 + 16 * 4 + CC * FP2 * 4 + 9 * 256 * 4)

__global__ __launch_bounds__(256) void k_iter0(const float* __restrict__ x) {
    extern __shared__ u64 smu[];
    u64*   cent2 = smu;                       // [k][cp] packed {c[2cp], c[2cp+1]}
    float* c2s   = (float*)(smu + 288);
    float* feats = c2s + 16;                  // [c][FP2]
    float* aff   = feats + CC * FP2;          // [k][256]

    int blk = blockIdx.x;
    int b = blk >> 8, bi = (blk >> 4) & 15, bj = blk & 15;
    int t = threadIdx.x;

    bool vk[9];
    #pragma unroll
    for (int k = 0; k < 9; k++) {
        int si = bi + k / 3 - 1, sj = bj + k % 3 - 1;
        vk[k] = ((unsigned)si < 16u) && ((unsigned)sj < 16u);
    }

    for (int u = t; u < 288; u += 256) {
        int k = u >> 5, cp = u & 31;
        int si = bi + k / 3 - 1, sj = bj + k % 3 - 1;
        float v0 = 0.f, v1 = 0.f;
        if (((unsigned)si < 16u) && ((unsigned)sj < 16u)) {
            const float* cp0 = &g_cent[(((b << 8) + (si << 4) + sj) << 6) + 2 * cp];
            v0 = cp0[0]; v1 = cp0[1];
        }
        cent2[u] = pack2(v0, v1);
    }
    __syncthreads();
    if (t < 9) {
        float s = 0.f;
        for (int cp = 0; cp < 32; cp++) {
            float lo, hi; unpack2(cent2[t * 32 + cp], lo, hi);
            s += lo * lo + hi * hi;
        }
        c2s[t] = s;
    }
    __syncthreads();

    // stage 1: per-pixel dots (channel-pair packed)
    const float* xp = x + (size_t)b * CC * PP
                        + (size_t)(bi * 16 + (t >> 4)) * WW + (bj * 16 + (t & 15));
    u64 dot[9]; u64 f2p = 0;
    #pragma unroll
    for (int k = 0; k < 9; k++) dot[k] = 0;
    #pragma unroll 8
    for (int cp = 0; cp < 32; cp++) {
        float f0 = xp[(2 * cp)     * PP];
        float f1 = xp[(2 * cp + 1) * PP];
        feats[(2 * cp)     * FP2 + t] = f0;
        feats[(2 * cp + 1) * FP2 + t] = f1;
        u64 fp = pack2(f0, f1);
        #pragma unroll
        for (int k = 0; k < 9; k++) ffma2(dot[k], fp, cent2[k * 32 + cp]);
        ffma2(f2p, fp, fp);
    }
    float f2; { float lo, hi; unpack2(f2p, lo, hi); f2 = lo + hi; }

    float m = -1e30f, lg[9];
    #pragma unroll
    for (int k = 0; k < 9; k++) {
        float lo, hi; unpack2(dot[k], lo, hi);
        float d = lo + hi;
        float l = vk[k] ? -(f2 + c2s[k] - 2.f * d) : -1e30f;
        lg[k] = l; m = fmaxf(m, l);
    }
    float esum = 0.f, ev[9];
    #pragma unroll
    for (int k = 0; k < 9; k++) {
        float e = vk[k] ? __expf(lg[k] - m) : 0.f;
        ev[k] = e; esum += e;
    }
    float inv = 1.f / esum;
    #pragma unroll
    for (int k = 0; k < 9; k++) aff[k * 256 + t] = ev[k] * inv;
    __syncthreads();

    // stage 2: num[k][c] = sum_p aff[k][p]*feats[c][p]  (pixel-pair packed)
    if (t < 128) {
        int c0 = t & 31, g = t >> 5;          // channels c0, c0+32; pixels [g*64, g*64+64)
        u64 acc0[9], acc1[9];
        #pragma unroll
        for (int k = 0; k < 9; k++) { acc0[k] = 0; acc1[k] = 0; }
        int pbase = g << 6;
        #pragma unroll 4
        for (int pp = 0; pp < 32; pp++) {
            int p = pbase + 2 * pp;
            u64 fa = *(const u64*)&feats[c0 * FP2 + p];
            u64 fb = *(const u64*)&feats[(c0 + 32) * FP2 + p];
            #pragma unroll
            for (int k = 0; k < 9; k++) {
                u64 a = *(const u64*)&aff[k * 256 + p];
                ffma2(acc0[k], a, fa);
                ffma2(acc1[k], a, fb);
            }
        }
        #pragma unroll
        for (int k = 0; k < 9; k++) {
            if (vk[k]) {
                int si = bi + k / 3 - 1, sj = bj + k % 3 - 1;
                int sidx = (b << 8) + (si << 4) + sj;
                float lo, hi;
                unpack2(acc0[k], lo, hi); atomicAdd(&g_num[(sidx << 6) + c0], lo + hi);
                unpack2(acc1[k], lo, hi); atomicAdd(&g_num[(sidx << 6) + c0 + 32], lo + hi);
            }
        }
    } else {
        int t2 = t - 128;                     // den: 72 threads, (k, 32-pixel chunk)
        if (t2 < 72) {
            int k = t2 >> 3, g8 = t2 & 7;
            if (vk[k]) {
                u64 one2 = pack2(1.f, 1.f), acc = 0;
                int pbase = g8 << 5;
                #pragma unroll
                for (int pp = 0; pp < 16; pp++) {
                    u64 a = *(const u64*)&aff[k * 256 + pbase + 2 * pp];
                    ffma2(acc, a, one2);
                }
                int si = bi + k / 3 - 1, sj = bj + k % 3 - 1;
                int sidx = (b << 8) + (si << 4) + sj;
                float lo, hi; unpack2(acc, lo, hi);
                atomicAdd(&g_den[sidx], lo + hi);
            }
        }
    }
}

// ---------------- K3: centroid update -------------------------------------
__global__ __launch_bounds__(256) void k_centup() {
    int e = blockIdx.x * 256 + threadIdx.x;
    g_cent[e] = g_num[e] / (g_den[e >> 6] + 1e-16f);
}

// ---------------- K4: affinity iter1 (4 tiles/CTA, 4 px/thread) -----------
__global__ __launch_bounds__(256) void k_iter1(const float* __restrict__ x) {
    __shared__ u64   cent2[4][9][64];         // packed {v,v}
    __shared__ float c2s[4][9];

    int t = threadIdx.x;
    int base_tile = blockIdx.x * 4;

    for (int u = t; u < 4 * 9 * 64; u += 256) {
        int tg = u / 576, rem = u - tg * 576;
        int k = rem >> 6, c = rem & 63;
        int tile = base_tile + tg;
        int b = tile >> 8, bi = (tile >> 4) & 15, bj = tile & 15;
        int si = bi + k / 3 - 1, sj = bj + k % 3 - 1;
        float v = 0.f;
        if (((unsigned)si < 16u) && ((unsigned)sj < 16u))
            v = g_cent[(((b << 8) + (si << 4) + sj) << 6) + c];
        cent2[tg][k][c] = pack2(v, v);
    }
    __syncthreads();
    if (t < 36) {
        int tg = t / 9, k = t - tg * 9;
        float s = 0.f;
        for (int c = 0; c < 64; c++) {
            float lo, hi; unpack2(cent2[tg][k][c], lo, hi);
            s += lo * lo;
        }
        c2s[tg][k] = s;
    }
    __syncthreads();

    int tg = t >> 6, u = t & 63;
    int tile = base_tile + tg;
    int b = tile >> 8, bi = (tile >> 4) & 15, bj = tile & 15;
    int li = u >> 2, jq = (u & 3) << 2;
    int gi = bi * 16 + li, gj = bj * 16 + jq;

    bool vk[9];
    #pragma unroll
    for (int k = 0; k < 9; k++) {
        int si = bi + k / 3 - 1, sj = bj + k % 3 - 1;
        vk[k] = ((unsigned)si < 16u) && ((unsigned)sj < 16u);
    }

    const float4* xp = (const float4*)(x + (size_t)b * CC * PP + (size_t)gi * WW + gj);
    u64 dota[9], dotb[9], f2a = 0, f2b = 0;
    #pragma unroll
    for (int k = 0; k < 9; k++) { dota[k] = 0; dotb[k] = 0; }

    #pragma unroll 8
    for (int c = 0; c < 64; c++) {
        float4 f = xp[c * (PP >> 2)];
        u64 fa = pack2(f.x, f.y), fb = pack2(f.z, f.w);
        #pragma unroll
        for (int k = 0; k < 9; k++) {
            u64 cv = cent2[tg][k][c];
            ffma2(dota[k], fa, cv);
            ffma2(dotb[k], fb, cv);
        }
        ffma2(f2a, fa, fa); ffma2(f2b, fb, fb);
    }

    float d[4][9], ff2[4];
    #pragma unroll
    for (int k = 0; k < 9; k++) {
        unpack2(dota[k], d[0][k], d[1][k]);
        unpack2(dotb[k], d[2][k], d[3][k]);
    }
    unpack2(f2a, ff2[0], ff2[1]);
    unpack2(f2b, ff2[2], ff2[3]);

    float e[4][9];
    #pragma unroll
    for (int px = 0; px < 4; px++) {
        float m = -1e30f, lg[9];
        #pragma unroll
        for (int k = 0; k < 9; k++) {
            float l = vk[k] ? -(ff2[px] + c2s[tg][k] - 2.f * d[px][k]) : -1e30f;
            lg[k] = l; m = fmaxf(m, l);
        }
        float s = 0.f;
        #pragma unroll
        for (int k = 0; k < 9; k++) {
            float evv = vk[k] ? __expf(lg[k] - m) : 0.f;
            e[px][k] = evv; s += evv;
        }
        float inv = 1.f / s;
        #pragma unroll
        for (int k = 0; k < 9; k++) e[px][k] *= inv;
    }
    size_t pbase = (size_t)gi * 256 + gj;
    #pragma unroll
    for (int k = 0; k < 9; k++) {
        *(float4*)&g_aff[((size_t)(b * 9 + k) << 16) + pbase] =
            make_float4(e[0][k], e[1][k], e[2][k], e[3][k]);
    }
}

// ---------------- K5: dense scatter ---------------------------------------
__global__ __launch_bounds__(256) void k_scatter(float* __restrict__ out) {
    int row = blockIdx.y;                     // b*256 + s
    int b = row >> 8, s = row & 255;
    int si = s >> 4, sj = s & 15;
    int idx = blockIdx.x * 256 + threadIdx.x; // float4 index
    int p = idx << 2;
    int i = p >> 8, j = p & 255;
    int di = si - (i >> 4), dj = sj - (j >> 4);

    float4 v = make_float4(0.f, 0.f, 0.f, 0.f);
    if (di >= -1 && di <= 1 && dj >= -1 && dj <= 1) {
        int k = (di + 1) * 3 + (dj + 1);
        v = *(const float4*)&g_aff[((size_t)(b * 9 + k) << 16) + p];
    }
    *(float4*)&out[((size_t)row << 16) + p] = v;
}

// ---------------- launch ---------------------------------------------------
extern "C" void kernel_launch(void* const* d_in, const int* in_sizes, int n_in,
                              void* d_out, int out_size) {
    const float* x = (const float*)d_in[0];
    float* out = (float*)d_out;

    cudaFuncSetAttribute(k_iter0, cudaFuncAttributeMaxDynamicSharedMemorySize, SM0_BYTES);

    k_cent0 <<<BB * NS, 256>>>(x);
    k_iter0 <<<BB * NS, 256, SM0_BYTES>>>(x);
    k_centup<<<(BB * NS * CC) / 256, 256>>>();
    k_iter1 <<<BB * NS / 4, 256>>>(x);
    dim3 g5(PP / 4 / 256, BB * NS);
    k_scatter<<<g5, 256>>>(out);
}

// round 5
// speedup vs baseline: 1.0684x; 1.0684x over previous
#include <cuda_runtime.h>

// GenSP superpixel affinity — GB300 sm_103a
// B=4, C=64, H=W=256, stoken=16 -> nH=nW=16, nS=256, P=65536
#define BB    4
#define CC    64
#define HH    256
#define WW    256
#define NHB   16
#define NS    256
#define PP    65536
#define FPW   33            // u64 per pixel row in iter0 feats smem (32 cpairs + pad)

typedef unsigned long long u64;

__device__ __forceinline__ u64 pack2(float lo, float hi) {
    u64 r; asm("mov.b64 %0, {%1,%2};" : "=l"(r) : "f"(lo), "f"(hi)); return r;
}
__device__ __forceinline__ void unpack2(u64 v, float& lo, float& hi) {
    asm("mov.b64 {%0,%1}, %2;" : "=f"(lo), "=f"(hi) : "l"(v));
}
__device__ __forceinline__ void ffma2(u64& d, u64 a, u64 b) {
    asm("fma.rn.f32x2 %0, %1, %2, %0;" : "+l"(d) : "l"(a), "l"(b));
}

// ---------------- device scratch ------------------------------------------
__device__ float g_cent[BB * NS * CC];
__device__ float g_num [BB * NS * CC];
__device__ float g_den [BB * NS];
__device__ float g_aff [BB * 9 * PP];     // iter-1 affinities [b][k][p]

// ---------------- K1: block means + zero num/den --------------------------
__global__ __launch_bounds__(256) void k_cent0(const float* __restrict__ x) {
    int blk = blockIdx.x;                  // b*256 + s
    int b = blk >> 8, s = blk & 255;
    int si = s >> 4, sj = s & 15;
    int t = threadIdx.x, w = t >> 5, lane = t & 31;

    if (t < CC)  g_num[blk * CC + t] = 0.f;
    if (t == CC) g_den[blk] = 0.f;

    const float* xb = x + (size_t)b * CC * PP + (size_t)(si * 16) * WW + sj * 16;
    #pragma unroll
    for (int cc = 0; cc < 8; cc++) {
        int c = w * 8 + cc;
        const float4* xc = (const float4*)(xb + (size_t)c * PP);
        float sum = 0.f;
        #pragma unroll
        for (int q = 0; q < 2; q++) {
            int i = lane + q * 32;
            int row = i >> 2, col = i & 3;
            float4 f = xc[row * (WW >> 2) + col];
            sum += (f.x + f.y) + (f.z + f.w);
        }
        #pragma unroll
        for (int o = 16; o; o >>= 1) sum += __shfl_xor_sync(0xffffffffu, sum, o);
        if (lane == 0) g_cent[blk * CC + c] = sum * (1.f / 256.f);
    }
}

// ---------------- K2: affinity iter0 + num/den (one tile per CTA) ---------
// smem (u64 units): cent2[288] | c2s[8 u64 = 16 floats] | feats[256*FPW] | aff2[9*256]
#define C2S_U64   8
#define SM0_U64   (288 + C2S_U64 + 256 * FPW + 9 * 256)
#define SM0_BYTES (SM0_U64 * 8)

__global__ __launch_bounds__(256) void k_iter0(const float* __restrict__ x) {
    extern __shared__ u64 smu[];
    u64*   cent2 = smu;                       // [k][cp] packed {c[2cp],c[2cp+1]}
    float* c2s   = (float*)(smu + 288);       // 9 floats (16 floats reserved)
    u64*   feats = smu + 288 + C2S_U64;       // [px][FPW] packed channel pairs
    u64*   aff2  = feats + 256 * FPW;         // [k][px] packed {a,a}

    int blk = blockIdx.x;
    int b = blk >> 8, bi = (blk >> 4) & 15, bj = blk & 15;
    int t = threadIdx.x;

    bool vk[9];
    #pragma unroll
    for (int k = 0; k < 9; k++) {
        int si = bi + k / 3 - 1, sj = bj + k % 3 - 1;
        vk[k] = ((unsigned)si < 16u) && ((unsigned)sj < 16u);
    }

    for (int u = t; u < 288; u += 256) {
        int k = u >> 5, cp = u & 31;
        int si = bi + k / 3 - 1, sj = bj + k % 3 - 1;
        float v0 = 0.f, v1 = 0.f;
        if (((unsigned)si < 16u) && ((unsigned)sj < 16u)) {
            const float* cp0 = &g_cent[(((b << 8) + (si << 4) + sj) << 6) + 2 * cp];
            v0 = cp0[0]; v1 = cp0[1];
        }
        cent2[u] = pack2(v0, v1);
    }
    __syncthreads();
    if (t < 9) {
        float s = 0.f;
        for (int cp = 0; cp < 32; cp++) {
            float lo, hi; unpack2(cent2[t * 32 + cp], lo, hi);
            s += lo * lo + hi * hi;
        }
        c2s[t] = s;
    }
    __syncthreads();

    // ---- stage 1: per-pixel dots (channel-pair packed) ----
    const float* xp = x + (size_t)b * CC * PP
                        + (size_t)(bi * 16 + (t >> 4)) * WW + (bj * 16 + (t & 15));
    u64 dot[9]; u64 f2p = 0;
    #pragma unroll
    for (int k = 0; k < 9; k++) dot[k] = 0;
    #pragma unroll 8
    for (int cp = 0; cp < 32; cp++) {
        float f0 = xp[(2 * cp)     * PP];
        float f1 = xp[(2 * cp + 1) * PP];
        u64 fp = pack2(f0, f1);
        feats[t * FPW + cp] = fp;
        #pragma unroll
        for (int k = 0; k < 9; k++) ffma2(dot[k], fp, cent2[k * 32 + cp]);
        ffma2(f2p, fp, fp);
    }
    float f2; { float lo, hi; unpack2(f2p, lo, hi); f2 = lo + hi; }

    float m = -1e30f, lg[9];
    #pragma unroll
    for (int k = 0; k < 9; k++) {
        float lo, hi; unpack2(dot[k], lo, hi);
        float d = lo + hi;
        float l = vk[k] ? -(f2 + c2s[k] - 2.f * d) : -1e30f;
        lg[k] = l; m = fmaxf(m, l);
    }
    float esum = 0.f, ev[9];
    #pragma unroll
    for (int k = 0; k < 9; k++) {
        float e = vk[k] ? __expf(lg[k] - m) : 0.f;
        ev[k] = e; esum += e;
    }
    float inv = 1.f / esum;
    #pragma unroll
    for (int k = 0; k < 9; k++) {
        float a = ev[k] * inv;
        aff2[k * 256 + t] = pack2(a, a);
    }
    __syncthreads();

    // ---- stage 2: num[k][2cp,2cp+1] over 32-px groups, all 256 threads ----
    {
        int cp = t & 31, g = t >> 5;          // channel pair cp, pixel group g (8x32)
        u64 acc[9];
        #pragma unroll
        for (int k = 0; k < 9; k++) acc[k] = 0;
        int pbase = g << 5;
        #pragma unroll 8
        for (int pp = 0; pp < 32; pp++) {
            int p = pbase + pp;
            u64 fv = feats[p * FPW + cp];
            #pragma unroll
            for (int k = 0; k < 9; k++) ffma2(acc[k], aff2[k * 256 + p], fv);
        }
        #pragma unroll
        for (int k = 0; k < 9; k++) {
            if (vk[k]) {
                int si = bi + k / 3 - 1, sj = bj + k % 3 - 1;
                int sidx = (b << 8) + (si << 4) + sj;
                float lo, hi; unpack2(acc[k], lo, hi);
                atomicAdd(&g_num[(sidx << 6) + 2 * cp],     lo);
                atomicAdd(&g_num[(sidx << 6) + 2 * cp + 1], hi);
            }
        }
    }
    // den: 72 threads, (k, 32-px chunk)
    if (t < 72) {
        int k = t >> 3, g8 = t & 7;
        if (vk[k]) {
            float a0 = 0.f, a1 = 0.f;
            int pbase = g8 << 5;
            #pragma unroll
            for (int pp = 0; pp < 16; pp++) {
                float lo, hi;
                unpack2(aff2[k * 256 + pbase + 2 * pp], lo, hi);     a0 += lo;
                unpack2(aff2[k * 256 + pbase + 2 * pp + 1], lo, hi); a1 += lo;
            }
            int si = bi + k / 3 - 1, sj = bj + k % 3 - 1;
            int sidx = (b << 8) + (si << 4) + sj;
            atomicAdd(&g_den[sidx], a0 + a1);
        }
    }
}

// ---------------- K3: centroid update -------------------------------------
__global__ __launch_bounds__(256) void k_centup() {
    int e = blockIdx.x * 256 + threadIdx.x;
    g_cent[e] = g_num[e] / (g_den[e >> 6] + 1e-16f);
}

// ---------------- K4: affinity iter1 (1 tile/CTA, channel-pair packed) ----
__global__ __launch_bounds__(256) void k_iter1(const float* __restrict__ x) {
    __shared__ u64   cent2[288];
    __shared__ float c2s[16];

    int blk = blockIdx.x;
    int b = blk >> 8, bi = (blk >> 4) & 15, bj = blk & 15;
    int t = threadIdx.x;

    bool vk[9];
    #pragma unroll
    for (int k = 0; k < 9; k++) {
        int si = bi + k / 3 - 1, sj = bj + k % 3 - 1;
        vk[k] = ((unsigned)si < 16u) && ((unsigned)sj < 16u);
    }

    for (int u = t; u < 288; u += 256) {
        int k = u >> 5, cp = u & 31;
        int si = bi + k / 3 - 1, sj = bj + k % 3 - 1;
        float v0 = 0.f, v1 = 0.f;
        if (((unsigned)si < 16u) && ((unsigned)sj < 16u)) {
            const float* cp0 = &g_cent[(((b << 8) + (si << 4) + sj) << 6) + 2 * cp];
            v0 = cp0[0]; v1 = cp0[1];
        }
        cent2[u] = pack2(v0, v1);
    }
    __syncthreads();
    if (t < 9) {
        float s = 0.f;
        for (int cp = 0; cp < 32; cp++) {
            float lo, hi; unpack2(cent2[t * 32 + cp], lo, hi);
            s += lo * lo + hi * hi;
        }
        c2s[t] = s;
    }
    __syncthreads();

    const float* xp = x + (size_t)b * CC * PP
                        + (size_t)(bi * 16 + (t >> 4)) * WW + (bj * 16 + (t & 15));
    u64 dot[9]; u64 f2p = 0;
    #pragma unroll
    for (int k = 0; k < 9; k++) dot[k] = 0;
    #pragma unroll 8
    for (int cp = 0; cp < 32; cp++) {
        float f0 = xp[(2 * cp)     * PP];
        float f1 = xp[(2 * cp + 1) * PP];
        u64 fp = pack2(f0, f1);
        #pragma unroll
        for (int k = 0; k < 9; k++) ffma2(dot[k], fp, cent2[k * 32 + cp]);
        ffma2(f2p, fp, fp);
    }
    float f2; { float lo, hi; unpack2(f2p, lo, hi); f2 = lo + hi; }

    float m = -1e30f, lg[9];
    #pragma unroll
    for (int k = 0; k < 9; k++) {
        float lo, hi; unpack2(dot[k], lo, hi);
        float d = lo + hi;
        float l = vk[k] ? -(f2 + c2s[k] - 2.f * d) : -1e30f;
        lg[k] = l; m = fmaxf(m, l);
    }
    float esum = 0.f, ev[9];
    #pragma unroll
    for (int k = 0; k < 9; k++) {
        float e = vk[k] ? __expf(lg[k] - m) : 0.f;
        ev[k] = e; esum += e;
    }
    float inv = 1.f / esum;

    int pg = (bi * 16 + (t >> 4)) * WW + (bj * 16 + (t & 15));
    #pragma unroll
    for (int k = 0; k < 9; k++)
        g_aff[((b * 9 + k) << 16) + pg] = ev[k] * inv;
}

// ---------------- K5: dense scatter (2x float4/thread, streaming) ---------
__global__ __launch_bounds__(256) void k_scatter(float* __restrict__ out) {
    int row = blockIdx.y;                     // b*256 + s
    int b = row >> 8, s = row & 255;
    int si = s >> 4, sj = s & 15;
    int idx = blockIdx.x * 256 + threadIdx.x; // 8-float chunk index
    int p = idx << 3;
    int i = p >> 8, j = p & 255;
    int di = si - (i >> 4), dj = sj - (j >> 4);

    float4 v0 = make_float4(0.f, 0.f, 0.f, 0.f);
    float4 v1 = v0;
    if (di >= -1 && di <= 1 && dj >= -1 && dj <= 1) {
        int k = (di + 1) * 3 + (dj + 1);
        const float4* src = (const float4*)&g_aff[((size_t)(b * 9 + k) << 16) + p];
        v0 = __ldcs(src); v1 = __ldcs(src + 1);
    }
    float4* dst = (float4*)&out[((size_t)row << 16) + p];
    __stcs(dst, v0); __stcs(dst + 1, v1);
}

// ---------------- launch ---------------------------------------------------
extern "C" void kernel_launch(void* const* d_in, const int* in_sizes, int n_in,
                              void* d_out, int out_size) {
    const float* x = (const float*)d_in[0];
    float* out = (float*)d_out;

    cudaFuncSetAttribute(k_iter0, cudaFuncAttributeMaxDynamicSharedMemorySize, SM0_BYTES);

    k_cent0 <<<BB * NS, 256>>>(x);
    k_iter0 <<<BB * NS, 256, SM0_BYTES>>>(x);
    k_centup<<<(BB * NS * CC) / 256, 256>>>();
    k_iter1 <<<BB * NS, 256>>>(x);
    dim3 g5(PP / 8 / 256, BB * NS);
    k_scatter<<<g5, 256>>>(out);
}

// round 6
// speedup vs baseline: 1.1886x; 1.1125x over previous
#include <cuda_runtime.h>

// GenSP superpixel affinity — GB300 sm_103a
// B=4, C=64, H=W=256, stoken=16 -> nH=nW=16, nS=256, P=65536
#define BB    4
#define CC    64
#define HH    256
#define WW    256
#define NHB   16
#define NS    256
#define PP    65536
#define FPW   33            // u64 per pixel row in iter0 feats smem (32 cpairs + pad)

// output zero-fill split (float4 units). total = 4*256*65536/4 = 16,777,216
#define ZQ_CENT0   2048     // float4 per cent0 CTA  (1024 CTAs -> 1/8 of out)
#define ZQ_ITER0   14336    // float4 per iter0 CTA  (1024 CTAs -> 7/8 of out)

typedef unsigned long long u64;

__device__ __forceinline__ u64 pack2(float lo, float hi) {
    u64 r; asm("mov.b64 %0, {%1,%2};" : "=l"(r) : "f"(lo), "f"(hi)); return r;
}
__device__ __forceinline__ void unpack2(u64 v, float& lo, float& hi) {
    asm("mov.b64 {%0,%1}, %2;" : "=f"(lo), "=f"(hi) : "l"(v));
}
__device__ __forceinline__ void ffma2(u64& d, u64 a, u64 b) {
    asm("fma.rn.f32x2 %0, %1, %2, %0;" : "+l"(d) : "l"(a), "l"(b));
}

// ---------------- device scratch ------------------------------------------
__device__ float g_cent[BB * NS * CC];
__device__ float g_num [BB * NS * CC];
__device__ float g_den [BB * NS];

// ---------------- K1: block means + zero num/den + zero 1/8 of out --------
__global__ __launch_bounds__(256) void k_cent0(const float* __restrict__ x,
                                               float* __restrict__ out) {
    int blk = blockIdx.x;                  // b*256 + s
    int b = blk >> 8, s = blk & 255;
    int si = s >> 4, sj = s & 15;
    int t = threadIdx.x, w = t >> 5, lane = t & 31;

    // fire-and-forget zero stores (first 1/8 of output)
    {
        float4 z = make_float4(0.f, 0.f, 0.f, 0.f);
        float4* oz = (float4*)out + (size_t)blk * ZQ_CENT0;
        #pragma unroll
        for (int i = 0; i < ZQ_CENT0 / 256; i++)
            __stcs(oz + i * 256 + t, z);
    }

    if (t < CC)  g_num[blk * CC + t] = 0.f;
    if (t == CC) g_den[blk] = 0.f;

    const float* xb = x + (size_t)b * CC * PP + (size_t)(si * 16) * WW + sj * 16;
    #pragma unroll
    for (int cc = 0; cc < 8; cc++) {
        int c = w * 8 + cc;
        const float4* xc = (const float4*)(xb + (size_t)c * PP);
        float sum = 0.f;
        #pragma unroll
        for (int q = 0; q < 2; q++) {
            int i = lane + q * 32;
            int row = i >> 2, col = i & 3;
            float4 f = xc[row * (WW >> 2) + col];
            sum += (f.x + f.y) + (f.z + f.w);
        }
        #pragma unroll
        for (int o = 16; o; o >>= 1) sum += __shfl_xor_sync(0xffffffffu, sum, o);
        if (lane == 0) g_cent[blk * CC + c] = sum * (1.f / 256.f);
    }
}

// ---------------- K2: affinity iter0 + num/den + zero 7/8 of out ----------
// smem (u64 units): cent2[288] | c2s[8 u64 = 16 floats] | feats[256*FPW] | aff2[9*256]
#define C2S_U64   8
#define SM0_U64   (288 + C2S_U64 + 256 * FPW + 9 * 256)
#define SM0_BYTES (SM0_U64 * 8)

__global__ __launch_bounds__(256) void k_iter0(const float* __restrict__ x,
                                               float* __restrict__ out) {
    extern __shared__ u64 smu[];
    u64*   cent2 = smu;                       // [k][cp] packed {c[2cp],c[2cp+1]}
    float* c2s   = (float*)(smu + 288);       // 9 floats (16 reserved)
    u64*   feats = smu + 288 + C2S_U64;       // [px][FPW] packed channel pairs
    u64*   aff2  = feats + 256 * FPW;         // [k][px] packed {a,a}

    int blk = blockIdx.x;
    int b = blk >> 8, bi = (blk >> 4) & 15, bj = blk & 15;
    int t = threadIdx.x;

    // fire-and-forget zero stores (remaining 7/8 of output)
    {
        float4 z = make_float4(0.f, 0.f, 0.f, 0.f);
        float4* oz = (float4*)out + (size_t)1024 * ZQ_CENT0 + (size_t)blk * ZQ_ITER0;
        #pragma unroll
        for (int i = 0; i < ZQ_ITER0 / 256; i++)
            __stcs(oz + i * 256 + t, z);
    }

    bool vk[9];
    #pragma unroll
    for (int k = 0; k < 9; k++) {
        int si = bi + k / 3 - 1, sj = bj + k % 3 - 1;
        vk[k] = ((unsigned)si < 16u) && ((unsigned)sj < 16u);
    }

    for (int u = t; u < 288; u += 256) {
        int k = u >> 5, cp = u & 31;
        int si = bi + k / 3 - 1, sj = bj + k % 3 - 1;
        float v0 = 0.f, v1 = 0.f;
        if (((unsigned)si < 16u) && ((unsigned)sj < 16u)) {
            const float* cp0 = &g_cent[(((b << 8) + (si << 4) + sj) << 6) + 2 * cp];
            v0 = cp0[0]; v1 = cp0[1];
        }
        cent2[u] = pack2(v0, v1);
    }
    __syncthreads();
    if (t < 9) {
        float s = 0.f;
        for (int cp = 0; cp < 32; cp++) {
            float lo, hi; unpack2(cent2[t * 32 + cp], lo, hi);
            s += lo * lo + hi * hi;
        }
        c2s[t] = s;
    }
    __syncthreads();

    // ---- stage 1: per-pixel dots (channel-pair packed) ----
    const float* xp = x + (size_t)b * CC * PP
                        + (size_t)(bi * 16 + (t >> 4)) * WW + (bj * 16 + (t & 15));
    u64 dot[9]; u64 f2p = 0;
    #pragma unroll
    for (int k = 0; k < 9; k++) dot[k] = 0;
    #pragma unroll 8
    for (int cp = 0; cp < 32; cp++) {
        float f0 = xp[(2 * cp)     * PP];
        float f1 = xp[(2 * cp + 1) * PP];
        u64 fp = pack2(f0, f1);
        feats[t * FPW + cp] = fp;
        #pragma unroll
        for (int k = 0; k < 9; k++) ffma2(dot[k], fp, cent2[k * 32 + cp]);
        ffma2(f2p, fp, fp);
    }
    float f2; { float lo, hi; unpack2(f2p, lo, hi); f2 = lo + hi; }

    float m = -1e30f, lg[9];
    #pragma unroll
    for (int k = 0; k < 9; k++) {
        float lo, hi; unpack2(dot[k], lo, hi);
        float d = lo + hi;
        float l = vk[k] ? -(f2 + c2s[k] - 2.f * d) : -1e30f;
        lg[k] = l; m = fmaxf(m, l);
    }
    float esum = 0.f, ev[9];
    #pragma unroll
    for (int k = 0; k < 9; k++) {
        float e = vk[k] ? __expf(lg[k] - m) : 0.f;
        ev[k] = e; esum += e;
    }
    float inv = 1.f / esum;
    #pragma unroll
    for (int k = 0; k < 9; k++) {
        float a = ev[k] * inv;
        aff2[k * 256 + t] = pack2(a, a);
    }
    __syncthreads();

    // ---- stage 2: num[k][2cp,2cp+1] over 32-px groups, all 256 threads ----
    {
        int cp = t & 31, g = t >> 5;          // channel pair cp, pixel group g (8x32)
        u64 acc[9];
        #pragma unroll
        for (int k = 0; k < 9; k++) acc[k] = 0;
        int pbase = g << 5;
        #pragma unroll 8
        for (int pp = 0; pp < 32; pp++) {
            int p = pbase + pp;
            u64 fv = feats[p * FPW + cp];
            #pragma unroll
            for (int k = 0; k < 9; k++) ffma2(acc[k], aff2[k * 256 + p], fv);
        }
        #pragma unroll
        for (int k = 0; k < 9; k++) {
            if (vk[k]) {
                int si = bi + k / 3 - 1, sj = bj + k % 3 - 1;
                int sidx = (b << 8) + (si << 4) + sj;
                float lo, hi; unpack2(acc[k], lo, hi);
                atomicAdd(&g_num[(sidx << 6) + 2 * cp],     lo);
                atomicAdd(&g_num[(sidx << 6) + 2 * cp + 1], hi);
            }
        }
    }
    // den: 72 threads, (k, 32-px chunk)
    if (t < 72) {
        int k = t >> 3, g8 = t & 7;
        if (vk[k]) {
            float a0 = 0.f, a1 = 0.f;
            int pbase = g8 << 5;
            #pragma unroll
            for (int pp = 0; pp < 16; pp++) {
                float lo, hi;
                unpack2(aff2[k * 256 + pbase + 2 * pp], lo, hi);     a0 += lo;
                unpack2(aff2[k * 256 + pbase + 2 * pp + 1], lo, hi); a1 += lo;
            }
            int si = bi + k / 3 - 1, sj = bj + k % 3 - 1;
            int sidx = (b << 8) + (si << 4) + sj;
            atomicAdd(&g_den[sidx], a0 + a1);
        }
    }
}

// ---------------- K3: centroid update -------------------------------------
__global__ __launch_bounds__(256) void k_centup() {
    int e = blockIdx.x * 256 + threadIdx.x;
    g_cent[e] = g_num[e] / (g_den[e >> 6] + 1e-16f);
}

// ---------------- K4: affinity iter1 fused with output scatter ------------
__global__ __launch_bounds__(256) void k_iter1f(const float* __restrict__ x,
                                                float* __restrict__ out) {
    __shared__ u64   cent2[288];
    __shared__ float c2s[16];

    int blk = blockIdx.x;
    int b = blk >> 8, bi = (blk >> 4) & 15, bj = blk & 15;
    int t = threadIdx.x;

    bool vk[9];
    #pragma unroll
    for (int k = 0; k < 9; k++) {
        int si = bi + k / 3 - 1, sj = bj + k % 3 - 1;
        vk[k] = ((unsigned)si < 16u) && ((unsigned)sj < 16u);
    }

    for (int u = t; u < 288; u += 256) {
        int k = u >> 5, cp = u & 31;
        int si = bi + k / 3 - 1, sj = bj + k % 3 - 1;
        float v0 = 0.f, v1 = 0.f;
        if (((unsigned)si < 16u) && ((unsigned)sj < 16u)) {
            const float* cp0 = &g_cent[(((b << 8) + (si << 4) + sj) << 6) + 2 * cp];
            v0 = cp0[0]; v1 = cp0[1];
        }
        cent2[u] = pack2(v0, v1);
    }
    __syncthreads();
    if (t < 9) {
        float s = 0.f;
        for (int cp = 0; cp < 32; cp++) {
            float lo, hi; unpack2(cent2[t * 32 + cp], lo, hi);
            s += lo * lo + hi * hi;
        }
        c2s[t] = s;
    }
    __syncthreads();

    int gi = bi * 16 + (t >> 4), gj = bj * 16 + (t & 15);
    const float* xp = x + (size_t)b * CC * PP + (size_t)gi * WW + gj;
    u64 dot[9]; u64 f2p = 0;
    #pragma unroll
    for (int k = 0; k < 9; k++) dot[k] = 0;
    #pragma unroll 8
    for (int cp = 0; cp < 32; cp++) {
        float f0 = xp[(2 * cp)     * PP];
        float f1 = xp[(2 * cp + 1) * PP];
        u64 fp = pack2(f0, f1);
        #pragma unroll
        for (int k = 0; k < 9; k++) ffma2(dot[k], fp, cent2[k * 32 + cp]);
        ffma2(f2p, fp, fp);
    }
    float f2; { float lo, hi; unpack2(f2p, lo, hi); f2 = lo + hi; }

    float m = -1e30f, lg[9];
    #pragma unroll
    for (int k = 0; k < 9; k++) {
        float lo, hi; unpack2(dot[k], lo, hi);
        float d = lo + hi;
        float l = vk[k] ? -(f2 + c2s[k] - 2.f * d) : -1e30f;
        lg[k] = l; m = fmaxf(m, l);
    }
    float esum = 0.f, ev[9];
    #pragma unroll
    for (int k = 0; k < 9; k++) {
        float e = vk[k] ? __expf(lg[k] - m) : 0.f;
        ev[k] = e; esum += e;
    }
    float inv = 1.f / esum;

    // direct scatter to output: row = b*256 + cand_s, col = pixel index
    int pg = gi * WW + gj;
    #pragma unroll
    for (int k = 0; k < 9; k++) {
        if (vk[k]) {
            int si = bi + k / 3 - 1, sj = bj + k % 3 - 1;
            int row = (b << 8) + (si << 4) + sj;
            out[((size_t)row << 16) + pg] = ev[k] * inv;
        }
    }
}

// ---------------- launch ---------------------------------------------------
extern "C" void kernel_launch(void* const* d_in, const int* in_sizes, int n_in,
                              void* d_out, int out_size) {
    const float* x = (const float*)d_in[0];
    float* out = (float*)d_out;

    cudaFuncSetAttribute(k_iter0, cudaFuncAttributeMaxDynamicSharedMemorySize, SM0_BYTES);

    k_cent0 <<<BB * NS, 256>>>(x, out);
    k_iter0 <<<BB * NS, 256, SM0_BYTES>>>(x, out);
    k_centup<<<(BB * NS * CC) / 256, 256>>>();
    k_iter1f<<<BB * NS, 256>>>(x, out);
}